// round 13
// baseline (speedup 1.0000x reference)
#include <cuda_runtime.h>
#include <cuda_fp16.h>

#define NSEG   128
#define SDIM   32
#define TDIM   32
#define NWARPS 4
#define NTHREADS 128
#define SPLIT  13
#define NBINS  34                 // bin = r+1, r in [-1, 32]
#define PITCH  32                 // word addr = 32*bin + t  ->  bank = t (conflict-free)

__device__ float    g_scratch[NSEG * SDIM * TDIM];   // zero-init; self-cleaned
__device__ unsigned g_count[NSEG];                   // zero-init; self-cleaned

__device__ __forceinline__ long long ld_idx(const void* p, int i, bool is64) {
    return is64 ? ((const long long*)p)[i] : (long long)((const int*)p)[i];
}

__global__ void __launch_bounds__(NTHREADS, SPLIT)
ect_kernel(const float* __restrict__ x, const void* __restrict__ idxraw,
           const float* __restrict__ v, const float* __restrict__ lin,
           const void* __restrict__ scaleraw, float* __restrict__ out, int N)
{
    // per-warp accumulators: half2 {count, tanh-sum} per (bin, t)
    __shared__ __half2 acc[NWARPS][NBINS * PITCH];
    __shared__ float   tw[NWARPS][TDIM];
    __shared__ int     sbounds[2];
    __shared__ int     islast;

    const int tid = threadIdx.x;
    const int w   = tid >> 5;
    const int t   = tid & 31;
    const int seg  = (int)blockIdx.x / SPLIT;
    const int part = (int)blockIdx.x - seg * SPLIT;

    // zero accumulators, 16B-vectorized
    {
        int4* z = (int4*)&acc[0][0];
        const int n16 = (NWARPS * NBINS * PITCH) / 4;
        for (int i = tid; i < n16; i += NTHREADS)
            z[i] = make_int4(0, 0, 0, 0);
    }

    // warps 0/1: warp-cooperative 32-ary lower_bound for seg / seg+1
    const bool is64 = (((const int*)idxraw)[(N - 2) | 1] == 0);
    if (w < 2) {
        const long long T = (long long)(seg + w);
        int lo = 0, hi = N;
        long long first = ld_idx(idxraw, 0, is64);
        if (first >= T) {
            hi = 0;
        } else {
            // invariant: idx[lo] < T, answer in (lo, hi]
            while (hi - lo > 1) {
                long long span = (long long)(hi - lo);
                int pos = lo + (int)((span * (long long)t) >> 5);
                long long val = ld_idx(idxraw, pos, is64);
                unsigned m = __ballot_sync(0xFFFFFFFFu, val < T);
                int k = __popc(m);                 // >= 1 (lane 0 probes lo)
                int nl = lo + (int)((span * (long long)(k - 1)) >> 5);
                int nh = (k < 32) ? lo + (int)((span * (long long)k) >> 5) : hi;
                lo = nl; hi = nh;
            }
        }
        if (t == 0) sbounds[w] = hi;
    }
    __syncthreads();
    const int segS = sbounds[0];
    const int segE = sbounds[1];

    // scale: int32/int64 low word, or float32
    int s_i = *(const int*)scaleraw;
    const float scale = (s_i > 0 && s_i < 1000000) ? (float)s_i
                                                   : *(const float*)scaleraw;

    const float lin0   = lin[0];
    const float dl     = (lin[SDIM - 1] - lin0) * (1.0f / (SDIM - 1));
    const float inv_dl = 1.0f / dl;
    const float K2     = -0.5f * scale * dl;      // tanh arg scale
    const float nb     = -lin0 * inv_dl;
    const float MAGIC  = 12582912.0f;             // 2^23 + 2^22
    const unsigned MAGICI = 0x4B400000u;
    const float K2M    = K2 * MAGIC;

    // fold inv_dl into the projection: u = x . (v*inv_dl) + nb
    const float v0 = v[t] * inv_dl;
    const float v1 = v[TDIM + t] * inv_dl;
    const float v2 = v[2 * TDIM + t] * inv_dl;

    // bin -> smem byte address in ONE IMAD: off = bits(u+MAGIC)*128 + adj
    const unsigned sbase = (unsigned)__cvta_generic_to_shared(&acc[0][0]);
    const unsigned adj   = sbase + (unsigned)(w * NBINS * PITCH * 4)
                         + (unsigned)(t * 4) + 128u - MAGICI * 128u;  // mod 2^32

    const int chunk = (segE - segS + SPLIT - 1) / SPLIT;
    int start = segS + part * chunk;
    if (start > segE) start = segE;
    int end = start + chunk;
    if (end > segE) end = segE;

    int gs = (start + 3) & ~3;                    // first float4-aligned node
    if (gs > end) gs = end;
    const int ge = gs + ((end - gs) & ~3);

    // serial per-node RMW (LSU pipelines distinct-addr RMWs)
    auto proc = [&](float u) {
        u = fminf(fmaxf(u, -0.6f), 32.4f);
        float f = u + MAGIC;                       // rint via magic number
        float t1 = fmaf(f, -K2, K2M);              // = -K2*rint(u)
        float z  = fmaf(u, K2, t1);                // = K2*(u - rint(u))
        float th; asm("tanh.approx.f32 %0, %1;" : "=f"(th) : "f"(z));
        __half2 inc = __floats2half2_rn(1.0f, th); // {count, tanh}
        unsigned incu = *reinterpret_cast<unsigned*>(&inc);
        unsigned off = __float_as_uint(f) * 128u + adj;   // single IMAD
        unsigned cur;
        asm volatile("ld.shared.b32 %0, [%1];" : "=r"(cur) : "r"(off));
        __half2 ch = *reinterpret_cast<__half2*>(&cur);
        __half2 ih = *reinterpret_cast<__half2*>(&incu);
        ch = __hadd2(ch, ih);
        unsigned res = *reinterpret_cast<unsigned*>(&ch);
        asm volatile("st.shared.b32 [%0], %1;" :: "r"(off), "r"(res));
    };

    // main loop: 4 nodes/iter, 3x float4 broadcast loads
    for (int n = gs + w * 4; n < ge; n += NWARPS * 4) {
        const float4* xp = (const float4*)(x + 3 * n);
        float4 A = __ldg(xp), B = __ldg(xp + 1), C = __ldg(xp + 2);
        float u0 = fmaf(A.z, v2, fmaf(A.y, v1, fmaf(A.x, v0, nb)));
        float u1 = fmaf(B.y, v2, fmaf(B.x, v1, fmaf(A.w, v0, nb)));
        float u2 = fmaf(C.x, v2, fmaf(B.w, v1, fmaf(B.z, v0, nb)));
        float u3 = fmaf(C.w, v2, fmaf(C.z, v1, fmaf(C.y, v0, nb)));
        proc(u0); proc(u1); proc(u2); proc(u3);
    }
    // scalar remainders (<= 3 each side), warp 0
    if (w == 0) {
        for (int n = start; n < gs; n++) {
            const float* xp = x + 3 * n;
            proc(fmaf(__ldg(xp + 2), v2, fmaf(__ldg(xp + 1), v1,
                 fmaf(__ldg(xp), v0, nb))));
        }
        for (int n = ge; n < end; n++) {
            const float* xp = x + 3 * n;
            proc(fmaf(__ldg(xp + 2), v2, fmaf(__ldg(xp + 1), v1,
                 fmaf(__ldg(xp), v0, nb))));
        }
    }
    __syncthreads();

    // ---- parallel epilogue into scratch: warp w owns bins [bs, be] ----
    // contribution[b-1] = sum_{b'<b} C[b'] + 0.5*(C[b] + Th[b])
    float* sb = g_scratch + seg * (SDIM * TDIM);
    {
        const int bs = (w == 0) ? 0 : 8 * w + 1;
        const int be = 8 * w + 8;                  // inclusive

        float tot = 0.f;
        for (int b = bs; b <= be; b++) {
            int o = b * PITCH + t;
            float2 f0 = __half22float2(acc[0][o]);
            float2 f1 = __half22float2(acc[1][o]);
            float2 f2 = __half22float2(acc[2][o]);
            float2 f3 = __half22float2(acc[3][o]);
            tot += (f0.x + f1.x) + (f2.x + f3.x);
        }
        tw[w][t] = tot;
        __syncthreads();

        float run = 0.f;
        #pragma unroll
        for (int ww = 0; ww < NWARPS; ww++)
            if (ww < w) run += tw[ww][t];
        for (int b = bs; b <= be; b++) {
            int o = b * PITCH + t;
            float2 f0 = __half22float2(acc[0][o]);
            float2 f1 = __half22float2(acc[1][o]);
            float2 f2 = __half22float2(acc[2][o]);
            float2 f3 = __half22float2(acc[3][o]);
            float C  = (f0.x + f1.x) + (f2.x + f3.x);
            float Th = (f0.y + f1.y) + (f2.y + f3.y);
            if (b >= 1) atomicAdd(sb + (b - 1) * TDIM + t, fmaf(0.5f, C + Th, run));
            run += C;
        }
    }

    // ---- last-CTA-per-segment finalization (self-cleaning for graph replay) ----
    __threadfence();
    if (tid == 0) {
        unsigned old = atomicAdd(&g_count[seg], 1u);
        islast = (old == SPLIT - 1);
    }
    __syncthreads();
    if (islast) {
        __threadfence();   // acquire: all partners' REDs visible at L2
        float* ob = out + seg * (SDIM * TDIM);
        for (int i = tid; i < SDIM * TDIM; i += NTHREADS) {
            float val = __ldcg(sb + i);            // L2-coherent read
            ob[i] = val;
            sb[i] = 0.f;                           // reset for next replay
        }
        if (tid == 0) g_count[seg] = 0u;           // reset counter
    }
}

extern "C" void kernel_launch(void* const* d_in, const int* in_sizes, int n_in,
                              void* d_out, int out_size)
{
    const float* x     = (const float*)d_in[0];
    const void*  index = d_in[1];
    const float* v     = (const float*)d_in[2];
    const float* lin   = (const float*)d_in[3];
    const void*  scale = d_in[4];
    float*       out   = (float*)d_out;
    const int N = in_sizes[1];

    ect_kernel<<<NSEG * SPLIT, NTHREADS>>>(x, index, v, lin, scale, out, N);
}